// round 12
// baseline (speedup 1.0000x reference)
#include <cuda_runtime.h>
#include <cstdint>
#include <math.h>

// DotAttention: context[b,f] = sum_t softmax_t(<hd[b],he[b,t]>) * he[b,t,f]
// b=64, t=2048, f=1024, fp32.
//
// Single-pass online softmax, cp.async pipelined: each warp streams its
// token rows into a private 2-stage smem ring with LDGSTS, so DRAM loads
// never stall on the dot/shfl/exp dependency chain. Fused split-merge via
// atomic ticket (no second kernel).

#define BATCH   64
#define TOK     2048
#define FDIM    1024
#define F4      (FDIM / 4)      // 256 float4 per row
#define SPLITS  8
#define TCHUNK  (TOK / SPLITS)  // 256 tokens per CTA
#define NWARP   8               // 256 threads
#define TPW     (TCHUNK / NWARP) // 32 tokens per warp
#define RING_BYTES (NWARP * 2 * FDIM * 4)  // 64 KB dynamic smem

// Scratch (allocation-free __device__ globals)
__device__ float4 g_part_ctx[BATCH * SPLITS * F4];  // 2 MB
__device__ float  g_part_m[BATCH * SPLITS];
__device__ float  g_part_l[BATCH * SPLITS];
__device__ int    g_cnt[BATCH];                     // zero-init; self-resets

__device__ __forceinline__ void cp_row(uint32_t slot_addr, const float* src, int lane)
{
    // 4KB row: 8 rounds of 16B per lane, fully coalesced 512B per round.
#pragma unroll
    for (int r = 0; r < 8; r++) {
        const float4* p = (const float4*)src + r * 32 + lane;
        asm volatile("cp.async.cg.shared.global [%0], [%1], 16;\n"
                     :: "r"(slot_addr + r * 512 + lane * 16), "l"(p));
    }
}

__global__ __launch_bounds__(256, 2)
void dotattn_fused(const float* __restrict__ hd, const float* __restrict__ he,
                   float* __restrict__ out)
{
    extern __shared__ float4 ring[];   // [NWARP * 2 * F4]; merge overlays it

    const int b    = blockIdx.y;
    const int s    = blockIdx.x;
    const int tid  = threadIdx.x;
    const int lane = tid & 31;
    const int warp = tid >> 5;

    __shared__ float s_m[NWARP], s_l[NWARP];
    __shared__ int   s_last;

    // q slice in registers: lane owns f4 indices j*32+lane (matches v layout)
    float4 q4[8];
    {
        const float4* hd4 = (const float4*)(hd + (size_t)b * FDIM);
#pragma unroll
        for (int j = 0; j < 8; j++) q4[j] = hd4[j * 32 + lane];
    }

    const int t0 = s * TCHUNK + warp;            // this warp's tokens: t0 + i*8
    const float* he_b = he + (size_t)b * TOK * FDIM;

    float4* slot0 = ring + (warp * 2 + 0) * F4;
    float4* slot1 = ring + (warp * 2 + 1) * F4;
    const uint32_t a0 = (uint32_t)__cvta_generic_to_shared(slot0);
    const uint32_t a1 = (uint32_t)__cvta_generic_to_shared(slot1);

    // prologue: fill both stages
    cp_row(a0, he_b + (size_t)(t0 + 0 * NWARP) * FDIM, lane);
    asm volatile("cp.async.commit_group;\n");
    cp_row(a1, he_b + (size_t)(t0 + 1 * NWARP) * FDIM, lane);
    asm volatile("cp.async.commit_group;\n");

    float  m = -INFINITY;
    float  l = 0.0f;
    float4 acc[8];
#pragma unroll
    for (int j = 0; j < 8; j++) acc[j] = make_float4(0.f, 0.f, 0.f, 0.f);

    for (int i = 0; i < TPW; i++) {
        asm volatile("cp.async.wait_group 1;\n" ::: "memory");
        const float4* slot = (i & 1) ? slot1 : slot0;

        float4 v[8];
#pragma unroll
        for (int j = 0; j < 8; j++) v[j] = slot[j * 32 + lane];

        float sc = 0.0f;
#pragma unroll
        for (int j = 0; j < 8; j++)
            sc += v[j].x * q4[j].x + v[j].y * q4[j].y
                + v[j].z * q4[j].z + v[j].w * q4[j].w;
#pragma unroll
        for (int o = 16; o > 0; o >>= 1)
            sc += __shfl_xor_sync(0xffffffffu, sc, o);

        // refill this stage for token i+2 (loads overlap the softmax chain)
        if (i + 2 < TPW) {
            cp_row((i & 1) ? a1 : a0,
                   he_b + (size_t)(t0 + (i + 2) * NWARP) * FDIM, lane);
        }
        asm volatile("cp.async.commit_group;\n");  // uniform group count

        const float nm   = fmaxf(m, sc);
        const float corr = __expf(m - nm);   // exp(-inf)=0 on first iter
        const float w    = __expf(sc - nm);
        l = l * corr + w;
        m = nm;
#pragma unroll
        for (int j = 0; j < 8; j++) {
            acc[j].x = acc[j].x * corr + w * v[j].x;
            acc[j].y = acc[j].y * corr + w * v[j].y;
            acc[j].z = acc[j].z * corr + w * v[j].z;
            acc[j].w = acc[j].w * corr + w * v[j].w;
        }
    }

    asm volatile("cp.async.wait_group 0;\n" ::: "memory");
    __syncthreads();   // everyone done with ring; safe to overlay merge

    // ---- merge the 8 warps (s_acc overlays ring[0..8*F4)) ----
    float4* s_acc = ring;
#pragma unroll
    for (int j = 0; j < 8; j++) s_acc[warp * F4 + j * 32 + lane] = acc[j];
    if (lane == 0) { s_m[warp] = m; s_l[warp] = l; }
    __syncthreads();

    float M = s_m[0];
#pragma unroll
    for (int w2 = 1; w2 < NWARP; w2++) M = fmaxf(M, s_m[w2]);
    float L = 0.0f;
    float4 c = make_float4(0.f, 0.f, 0.f, 0.f);
#pragma unroll
    for (int w2 = 0; w2 < NWARP; w2++) {
        const float e = __expf(s_m[w2] - M);
        L += s_l[w2] * e;
        float4 a = s_acc[w2 * F4 + tid];
        c.x += a.x * e;
        c.y += a.y * e;
        c.z += a.z * e;
        c.w += a.w * e;
    }
    g_part_ctx[((size_t)b * SPLITS + s) * F4 + tid] = c;
    if (tid == 0) {
        g_part_m[b * SPLITS + s] = M;
        g_part_l[b * SPLITS + s] = L;
    }

    // ---- fused cross-split finalize: last CTA of batch b reduces ----
    __threadfence();   // release partials
    if (tid == 0) {
        const int prev = atomicAdd(&g_cnt[b], 1);
        s_last = (prev == SPLITS - 1);
    }
    __syncthreads();
    if (!s_last) return;

    __threadfence();   // acquire

    const int base = b * SPLITS;
    float gm = -INFINITY;
#pragma unroll
    for (int sp = 0; sp < SPLITS; sp++) gm = fmaxf(gm, g_part_m[base + sp]);

    float gl = 0.0f;
    float4 o = make_float4(0.f, 0.f, 0.f, 0.f);
#pragma unroll
    for (int sp = 0; sp < SPLITS; sp++) {
        const float e = __expf(g_part_m[base + sp] - gm);
        gl += g_part_l[base + sp] * e;
        float4 a = g_part_ctx[(size_t)(base + sp) * F4 + tid];
        o.x += a.x * e;
        o.y += a.y * e;
        o.z += a.z * e;
        o.w += a.w * e;
    }
    const float inv = 1.0f / gl;
    o.x *= inv; o.y *= inv; o.z *= inv; o.w *= inv;
    ((float4*)out)[(size_t)b * F4 + tid] = o;

    __syncthreads();
    if (tid == 0) g_cnt[b] = 0;   // reset for next graph replay
}

extern "C" void kernel_launch(void* const* d_in, const int* in_sizes, int n_in,
                              void* d_out, int out_size)
{
    const float* hd = (const float*)d_in[0];  // (64, 1024)
    const float* he = (const float*)d_in[1];  // (64, 2048, 1024)
    float* out = (float*)d_out;               // (64, 1024)

    cudaFuncSetAttribute(dotattn_fused,
                         cudaFuncAttributeMaxDynamicSharedMemorySize, RING_BYTES);
    dim3 grid(SPLITS, BATCH);
    dotattn_fused<<<grid, 256, RING_BYTES>>>(hd, he, out);
}